// round 4
// baseline (speedup 1.0000x reference)
#include <cuda_runtime.h>

#define IMG_W 512
#define IMG_H 512
#define PLANE (IMG_W * IMG_H)
#define RPT   8
#define STRIPS_PER_PLANE (IMG_H / RPT)   // 64

__device__ __forceinline__ float med3f(float a, float b, float c) {
    return fmaxf(fminf(a, b), fminf(fmaxf(a, b), c));
}

struct RawRow {
    float4 v;
    float l, r;
};

struct SortedRow {
    float lo0, lo1, lo2, lo3;
    float mi0, mi1, mi2, mi3;
    float hi0, hi1, hi2, hi3;
};

// Three independent loads: aligned float4 + two halo scalars (L1 hits from
// neighbor lanes' lines). y is already resolved — no reflect logic here.
__device__ __forceinline__ RawRow load_raw(const float* __restrict__ ip,
                                           int y, int x0, int xl, int xr) {
    const float* __restrict__ rp = ip + y * IMG_W;
    RawRow o;
    o.v = *(const float4*)(rp + x0);
    o.l = rp[xl];
    o.r = rp[xr];
    return o;
}

__device__ __forceinline__ SortedRow sort_row(const RawRow& rr) {
    float s0 = rr.l, s1 = rr.v.x, s2 = rr.v.y, s3 = rr.v.z, s4 = rr.v.w, s5 = rr.r;
    SortedRow o;
    #define SORT3(a_, b_, c_, LO, MI, HI) {            \
        float a = (a_), b = (b_), c = (c_), t;          \
        t = fminf(a, b); b = fmaxf(a, b); a = t;        \
        t = fminf(b, c); c = fmaxf(b, c); b = t;        \
        t = fminf(a, b); b = fmaxf(a, b); a = t;        \
        o.LO = a; o.MI = b; o.HI = c; }
    SORT3(s0, s1, s2, lo0, mi0, hi0);
    SORT3(s1, s2, s3, lo1, mi1, hi1);
    SORT3(s2, s3, s4, lo2, mi2, hi2);
    SORT3(s3, s4, s5, lo3, mi3, hi3);
    #undef SORT3
    return o;
}

__device__ __forceinline__ float tail(float lA, float lB, float lC,
                                      float mA, float mB, float mC,
                                      float hA, float hB, float hC) {
    float mx = fmaxf(fmaxf(lA, lB), lC);
    float mn = fminf(fminf(hA, hB), hC);
    float md = med3f(mA, mB, mC);
    return med3f(mx, md, mn);
}

__global__ __launch_bounds__(128, 8)
void MedianFilter2D_68745246540291_kernel(const float* __restrict__ in,
                                          float* __restrict__ out) {
    const int t     = threadIdx.x;               // 0..127
    const int strip = blockIdx.x;

    const int plane = strip >> 6;                // strip / STRIPS_PER_PLANE
    const int sy    = strip & (STRIPS_PER_PLANE - 1);
    const int y0    = sy * RPT;
    const int x0    = t * 4;

    const float* __restrict__ ip = in  + (size_t)plane * PLANE;
    float*       __restrict__ op = out + (size_t)plane * PLANE;

    // Horizontal halo columns (hoisted, loop-invariant; image-edge reflect folded in)
    const int xl = (t == 0)   ? 1         : x0 - 1;
    const int xr = (t == 127) ? IMG_W - 2 : x0 + 4;

    // Vertical reflect resolved ONCE per block: only the first/last strip's
    // halo rows can be out of range.
    const int ytop = (sy == 0)                    ? 1         : y0 - 1;
    const int ybot = (sy == STRIPS_PER_PLANE - 1) ? IMG_H - 2 : y0 + RPT;

    SortedRow A = sort_row(load_raw(ip, ytop, x0, xl, xr));
    SortedRow B = sort_row(load_raw(ip, y0,   x0, xl, xr));
    RawRow nxt  = load_raw(ip, y0 + 1, x0, xl, xr);

    #pragma unroll
    for (int i = 0; i < RPT; i++) {
        RawRow cur = nxt;
        if (i + 1 < RPT) {
            const int yn = (i + 2 == RPT) ? ybot : (y0 + i + 2);
            nxt = load_raw(ip, yn, x0, xl, xr);
        }

        SortedRow C = sort_row(cur);

        float4 res;
        res.x = tail(A.lo0, B.lo0, C.lo0, A.mi0, B.mi0, C.mi0, A.hi0, B.hi0, C.hi0);
        res.y = tail(A.lo1, B.lo1, C.lo1, A.mi1, B.mi1, C.mi1, A.hi1, B.hi1, C.hi1);
        res.z = tail(A.lo2, B.lo2, C.lo2, A.mi2, B.mi2, C.mi2, A.hi2, B.hi2, C.hi2);
        res.w = tail(A.lo3, B.lo3, C.lo3, A.mi3, B.mi3, C.mi3, A.hi3, B.hi3, C.hi3);

        *(float4*)(op + (size_t)(y0 + i) * IMG_W + x0) = res;

        A = B; B = C;   // register renaming under full unroll
    }
}

extern "C" void kernel_launch(void* const* d_in, const int* in_sizes, int n_in,
                              void* d_out, int out_size) {
    const float* image = (const float*)d_in[0];
    float* out = (float*)d_out;

    // One 8-row strip per 128-thread block: 48 planes * 64 strips = 3072 blocks.
    dim3 block(128, 1, 1);
    dim3 grid(48 * STRIPS_PER_PLANE, 1, 1);
    MedianFilter2D_68745246540291_kernel<<<grid, block>>>(image, out);
}